// round 7
// baseline (speedup 1.0000x reference)
#include <cuda_runtime.h>
#include <cstdint>
#include <math.h>

#define BB 16
#define TT 500
#define CC 2048
#define SN 64
#define SD 512
#define CLU 8                      // CTAs per den cluster
#define CPC (SD / CLU)             // 64 columns per den CTA

typedef unsigned long long ull;

__device__ float g_llh[2 * BB];    // [0..15] den, [16..31] num

__device__ __forceinline__ float warp_max(float v) {
#pragma unroll
    for (int o = 16; o > 0; o >>= 1) v = fmaxf(v, __shfl_xor_sync(0xffffffffu, v, o));
    return v;
}
__device__ __forceinline__ float warp_sum(float v) {
#pragma unroll
    for (int o = 16; o > 0; o >>= 1) v += __shfl_xor_sync(0xffffffffu, v, o);
    return v;
}
__device__ __forceinline__ float clip30(float v) {
    return fminf(fmaxf(v, -30.f), 30.f);
}
__device__ __forceinline__ uint32_t smem_u32(const void* p) {
    uint32_t a;
    asm("{ .reg .u64 t; cvta.to.shared.u64 t, %1; cvt.u32.u64 %0, t; }" : "=r"(a) : "l"(p));
    return a;
}
// R5-proven: mapa computed inline, scalar f32 remote store.
__device__ __forceinline__ void st_cluster_f32(uint32_t local_addr, int rank, float v) {
    uint32_t rem;
    asm volatile("mapa.shared::cluster.u32 %0, %1, %2;" : "=r"(rem) : "r"(local_addr), "r"(rank));
    asm volatile("st.shared::cluster.f32 [%0], %1;" :: "r"(rem), "f"(v) : "memory");
}
__device__ __forceinline__ void cluster_sync_() {
    asm volatile("barrier.cluster.arrive.aligned;" ::: "memory");
    asm volatile("barrier.cluster.wait.aligned;" ::: "memory");
}
__device__ __forceinline__ uint32_t ctarank_() {
    uint32_t r;
    asm("mov.u32 %0, %%cluster_ctarank;" : "=r"(r));
    return r;
}
// packed dual-fp32 fma: d = a * b + d (lanewise on the two 32-bit halves)
__device__ __forceinline__ void fma2(ull& d, ull a, ull b) {
    asm("fma.rn.f32x2 %0, %1, %2, %0;" : "+l"(d) : "l"(a), "l"(b));
}

// ---------------------------------------------------------------------------
// Denominator: one 8-CTA cluster per batch, state kept LINEAR (no per-step
// log/exp of the state vector):
//   u = w_{t-1} / m_{t-1};  w_t = (u @ P) * exp(em_t);  logC += log(m_{t-1})
// m = max(w) combined lazily from 16 warp-maxima pushed the previous step.
// P slice (512x64) in registers as 32 packed f32x2 per thread.
// DSMEM plumbing identical to the proven R5 kernel (inline mapa, f32 stores).
// ---------------------------------------------------------------------------
__device__ void den_path(const float* __restrict__ x, const int* __restrict__ seqlens,
                         const float* __restrict__ logA, const float* __restrict__ ls,
                         const float* __restrict__ lf, const int* __restrict__ ids_g) {
    __shared__ __align__(16) float wbuf[2][SD];      // scalar w, double-buffered
    __shared__ __align__(16) ull u2_sh[SD];          // packed {u,u} (per-step scratch)
    __shared__ __align__(16) ull red2[16 * 32];      // [rg][cp] -> cols {2cp,2cp+1}
    __shared__ float m_arr[2][16];                   // 8 CTAs x 2 producer warps
    __shared__ float warp_red[16];
    __shared__ float m_sh, scale_sh;

    const int tid  = threadIdx.x;
    const int lane = tid & 31, wid = tid >> 5;
    const int rg   = tid >> 5;          // row group 0..15 (32 rows each)
    const int cp   = tid & 31;          // column pair 0..31
    const int r    = (int)ctarank_();
    const int b    = blockIdx.x / CLU;
    const int j0   = r * CPC + 2 * cp;
    const int L    = seqlens[b];
    const float* xb = x + (size_t)b * TT * CC;

    // P slice in registers, packed per column pair
    ull pr[32];
#pragma unroll
    for (int k = 0; k < 32; ++k) {
        float2 p2;
        p2.x = __expf(logA[(size_t)(rg * 32 + k) * SD + j0]);
        p2.y = __expf(logA[(size_t)(rg * 32 + k) * SD + j0 + 1]);
        pr[k] = *(ull*)&p2;
    }

    // t = 0 init (threads 0..63 own this CTA's 64 columns)
    int myid = 0;
    float emn = 0.f, logC = 0.f;
    const int jcol = r * CPC + tid;     // valid when tid < 64
    if (tid < 64) {
        myid = ids_g[jcol];
        // w0 = exp(alpha0), alpha0 = log_start + em0 (|alpha0| bounded: safe)
        float w0 = __expf(ls[jcol] + clip30(xb[myid]));
#pragma unroll
        for (int q = 0; q < CLU; ++q)
            st_cluster_f32(smem_u32(&wbuf[0][jcol]), q, w0);
        float wm = warp_max(w0);
        if (lane == 0) {
#pragma unroll
            for (int q = 0; q < CLU; ++q)
                st_cluster_f32(smem_u32(&m_arr[0][r * 2 + wid]), q, wm);
        }
        emn = (L > 1) ? xb[CC + myid] : 0.f;
    }
    cluster_sync_();

    int p = 0;
    for (int t = 1; t < L; ++t) {
        // warp 0: combine 16 broadcast warp maxima from previous step
        if (tid < 32) {
            float v = (lane < 16) ? m_arr[p][lane] : 0.f;
            v = warp_max(v);
            if (lane == 0) { m_sh = v; scale_sh = __fdividef(1.0f, v); }
        }
        __syncthreads();
        // pack normalized state: u2_sh[tid] = {w*sc, w*sc}
        {
            float w = wbuf[p][tid] * scale_sh;
            float2 ww = make_float2(w, w);
            u2_sh[tid] = *(ull*)&ww;
        }
        float E = 0.f;
        if (tid < 64) {
            E = __expf(clip30(emn));                  // hides under pack/matvec
            if (t + 1 < L) emn = xb[(size_t)(t + 1) * CC + myid];
        }
        __syncthreads();

        // matvec partial: 32 rows x 2 cols, packed f32x2
        ull acc = 0ull;
        const ulonglong2* uu = (const ulonglong2*)&u2_sh[rg * 32];
#pragma unroll
        for (int k2 = 0; k2 < 16; ++k2) {
            ulonglong2 u = uu[k2];
            fma2(acc, u.x, pr[2 * k2]);
            fma2(acc, u.y, pr[2 * k2 + 1]);
        }
        red2[rg * 32 + cp] = acc;
        __syncthreads();

        if (tid < 64) {
            const float* rf = (const float*)red2;
            float v = 0.f;
#pragma unroll
            for (int g2 = 0; g2 < 16; ++g2) v += rf[g2 * 64 + tid];
            float wn = v * E;                         // unnormalized next state
#pragma unroll
            for (int q = 0; q < CLU; ++q)
                st_cluster_f32(smem_u32(&wbuf[1 - p][jcol]), q, wn);
            float wm = warp_max(wn);
            if (lane == 0) {
#pragma unroll
                for (int q = 0; q < CLU; ++q)
                    st_cluster_f32(smem_u32(&m_arr[1 - p][r * 2 + wid]), q, wm);
            }
            if (tid == 0) logC += __logf(m_sh);
        }
        cluster_sync_();
        p ^= 1;
    }

    // llh = logC + log(sum_j w[j] * exp(lf[j]));  rank 0 has full w
    if (r == 0) {
        float e = wbuf[p][tid] * __expf(lf[tid]);
        float ws = warp_sum(e);
        if (lane == 0) warp_red[wid] = ws;
        __syncthreads();
        if (tid == 0) {
            float s = 0.f;
            for (int i = 0; i < 16; ++i) s += warp_red[i];
            g_llh[b] = logC + __logf(s);
        }
    }
    cluster_sync_();   // no CTA exits while peers may still receive DSMEM traffic
}

// ---------------------------------------------------------------------------
// Numerator: per-batch FSM (S=64), same linear-state scheme, one CTA per batch.
// ---------------------------------------------------------------------------
__device__ void num_path(int b, const float* __restrict__ x,
                         const int* __restrict__ seqlens,
                         const float* __restrict__ logA,
                         const float* __restrict__ ls,
                         const float* __restrict__ lf,
                         const int* __restrict__ ids_g) {
    __shared__ __align__(16) float Pn[SN * SN];
    __shared__ float w_n[SN];
    __shared__ float redn[8][SN];
    __shared__ float wred[2];

    const int tid = threadIdx.x;
    const int lane = tid & 31;
    const int g = tid >> 6;              // row group 0..7 (8 rows each)
    const int col = tid & 63;
    const int L = seqlens[b];
    const float* xb = x + (size_t)b * TT * CC;

    for (int i = tid; i < SN * SN; i += 512)
        Pn[i] = __expf(logA[(size_t)b * SN * SN + i]);

    int myid = 0;
    float emn = 0.f, logC = 0.f;
    if (tid < SN) {
        myid = ids_g[b * SN + tid];
        float w0 = __expf(ls[b * SN + tid] + clip30(xb[myid]));
        w_n[tid] = w0;
        float wm = warp_max(w0);
        if (lane == 0) wred[tid >> 5] = wm;
        emn = (L > 1) ? xb[CC + myid] : 0.f;
    }
    __syncthreads();

    for (int t = 1; t < L; ++t) {
        float m = fmaxf(wred[0], wred[1]);
        float E = 0.f, sc = 0.f;
        if (tid < SN) {
            sc = __fdividef(1.0f, m);
            E = __expf(clip30(emn));
            if (t + 1 < L) emn = xb[(size_t)(t + 1) * CC + myid];
        }
        float acc = 0.f;
#pragma unroll
        for (int k = 0; k < 8; ++k)
            acc = fmaf(w_n[g * 8 + k], Pn[(g * 8 + k) * SN + col], acc);
        redn[g][col] = acc;
        __syncthreads();
        if (tid < SN) {
            float v = 0.f;
#pragma unroll
            for (int g2 = 0; g2 < 8; ++g2) v += redn[g2][tid];
            float w = v * sc * E;
            w_n[tid] = w;
            float wm = warp_max(w);
            if (lane == 0) wred[tid >> 5] = wm;
            if (tid == 0) logC += __logf(m);
        }
        __syncthreads();
    }

    if (tid < SN) {
        float e = w_n[tid] * __expf(lf[b * SN + tid]);
        float ws = warp_sum(e);
        if (lane == 0) wred[tid >> 5] = ws;
    }
    __syncthreads();
    if (tid == 0) g_llh[BB + b] = logC + __logf(wred[0] + wred[1]);
}

// Fused: clusters 0..15 (CTAs 0..127) = den; CTAs 128..143 = num batches 0..15.
__global__ void __launch_bounds__(512, 1) __cluster_dims__(CLU, 1, 1)
fused_kernel(const float* __restrict__ x, const int* __restrict__ seqlens,
             const float* __restrict__ num_logA, const float* __restrict__ num_ls,
             const float* __restrict__ num_lf, const int* __restrict__ num_ids,
             const float* __restrict__ den_logA, const float* __restrict__ den_ls,
             const float* __restrict__ den_lf, const int* __restrict__ den_ids) {
    if (blockIdx.x < BB * CLU)
        den_path(x, seqlens, den_logA, den_ls, den_lf, den_ids);
    else
        num_path(blockIdx.x - BB * CLU, x, seqlens, num_logA, num_ls, num_lf, num_ids);
}

__global__ void finalize_kernel(float* __restrict__ out) {
    float sden = 0.f, snum = 0.f;
    for (int i = 0; i < BB; ++i) {
        sden += g_llh[i];
        snum += g_llh[BB + i];
    }
    out[0] = -(snum - sden);
}

extern "C" void kernel_launch(void* const* d_in, const int* in_sizes, int n_in,
                              void* d_out, int out_size) {
    const float* x        = (const float*)d_in[0];
    const int*   seqlens  = (const int*)d_in[1];
    const float* num_logA = (const float*)d_in[2];
    const float* num_ls   = (const float*)d_in[3];
    const float* num_lf   = (const float*)d_in[4];
    const int*   num_ids  = (const int*)d_in[5];
    const float* den_logA = (const float*)d_in[6];
    const float* den_ls   = (const float*)d_in[7];
    const float* den_lf   = (const float*)d_in[8];
    const int*   den_ids  = (const int*)d_in[9];

    fused_kernel<<<BB * CLU + BB, 512>>>(x, seqlens, num_logA, num_ls, num_lf,
                                         num_ids, den_logA, den_ls, den_lf, den_ids);
    finalize_kernel<<<1, 1>>>((float*)d_out);
}